// round 7
// baseline (speedup 1.0000x reference)
#include <cuda_runtime.h>
#include <cuda_fp16.h>
#include <cstdint>

#define N_ROWS  131072
#define C_DIM   256
#define K_CODES 1024
#define NZQ     33554432
#define HWSZ    4096

#define ESCALE    4096.0f          // 2^12: lift emb splits out of fp16 subnormal range
#define EINVSCALE 0.000244140625f  // 2^-12 (exact)

// ---- device scratch ----
__device__ __half g_es[2u * K_CODES * C_DIM];        // emb fp16 2-splits of (e * 2^12)
__device__ float  g_e2[K_CODES];
__device__ float  g_z2[N_ROWS];
__device__ unsigned long long g_min[N_ROWS];         // packed (dist_bits<<32)|code
__device__ float  g_partial[1024];

__device__ __forceinline__ uint32_t smem_u32(const void* p){
  uint32_t a;
  asm("{ .reg .u64 t; cvta.to.shared.u64 t, %1; cvt.u32.u64 %0, t; }" : "=r"(a) : "l"(p));
  return a;
}
__device__ __forceinline__ uint32_t swz(uint32_t off){ return off ^ ((off >> 3) & 0x70); }

__device__ __forceinline__ void split2(float v, uint32_t &s0, uint32_t &s1){
  __half h0 = __float2half_rn(v);
  float r  = __fsub_rn(v, __half2float(h0));
  __half h1 = __float2half_rn(r);
  s0 = (uint32_t)__half_as_ushort(h0);
  s1 = (uint32_t)__half_as_ushort(h1);
}

#define CPASYNC16(dst, src) \
  asm volatile("cp.async.cg.shared.global [%0], [%1], 16;" :: "r"(dst), "l"(src))
#define CPCOMMIT() asm volatile("cp.async.commit_group;")

#define LDSM_X4(r0,r1,r2,r3,addr) \
  asm volatile("ldmatrix.sync.aligned.m8n8.x4.shared.b16 {%0,%1,%2,%3}, [%4];" \
    : "=r"(r0), "=r"(r1), "=r"(r2), "=r"(r3) : "r"(addr))

#define MMA16816(c0,c1,c2,c3,a0,a1,a2,a3,b0,b1) \
  asm volatile("mma.sync.aligned.m16n8k16.row.col.f32.f16.f16.f32 " \
    "{%0,%1,%2,%3}, {%4,%5,%6,%7}, {%8,%9}, {%0,%1,%2,%3};" \
    : "+f"(c0), "+f"(c1), "+f"(c2), "+f"(c3) \
    : "r"(a0), "r"(a1), "r"(a2), "r"(a3), "r"(b0), "r"(b1))

#define STS128(addr, a0, a1, a2, a3) \
  asm volatile("st.shared.v4.b32 [%0], {%1,%2,%3,%4};" :: "r"(addr), "r"(a0), "r"(a1), "r"(a2), "r"(a3) : "memory")

// ---------------- prep: emb fp16 splits (scaled) + ||e||^2 ----------------
__global__ void prep_e(const float* __restrict__ emb){
  int k = blockIdx.x, c = threadIdx.x;
  float v = emb[k * C_DIM + c];
  uint32_t s0, s1;
  split2(v * ESCALE, s0, s1);
  g_es[(0u * K_CODES + k) * C_DIM + c] = __ushort_as_half((unsigned short)s0);
  g_es[(1u * K_CODES + k) * C_DIM + c] = __ushort_as_half((unsigned short)s1);
  __shared__ float red[C_DIM];
  red[c] = __fmul_rn(v, v);
  __syncthreads();
  for (int s = 128; s > 0; s >>= 1){
    if (c < s) red[c] = __fadd_rn(red[c], red[c + s]);
    __syncthreads();
  }
  if (c == 0) g_e2[k] = red[0];
}

// ---------------- prep: ||z||^2 (sequential ascending c — bit-exact, proven) ----------------
__global__ __launch_bounds__(256) void prep_z2(const float* __restrict__ z){
  const int n = blockIdx.x * 256 + threadIdx.x;
  const int b = n >> 12, hw = n & 4095;
  const float* p = z + (size_t)b * (C_DIM * HWSZ) + hw;
  float acc = 0.f;
  #pragma unroll 8
  for (int c = 0; c < 256; ++c){
    float v = p[(size_t)c * HWSZ];
    acc = __fadd_rn(acc, __fmul_rn(v, v));
  }
  g_z2[n] = acc;
}

// ---------------- init: argmin keys (must run every launch) ----------------
__global__ void init_min(){
  g_min[blockIdx.x * 256 + threadIdx.x] = 0xFFFFFFFFFFFFFFFFull;
}

// ---------------- main: B-stationary persistent-slice GEMM + argmin ----------------
// smem: B[8 ch][2 s][128 code][32 c] = 128K resident | A[2 buf][8 ch][2 s][32 r][32 c] = 64K
#define SM_B     0
#define SM_A     131072
#define SM_TOTAL 196608

__global__ __launch_bounds__(256) void vq_main(const float* __restrict__ z){
  extern __shared__ char smem[];
  const uint32_t sb = smem_u32(smem);
  const int t = threadIdx.x, w = t >> 5, l = t & 31;
  const int slice = blockIdx.x & 7, rblk = blockIdx.x >> 3;
  const int nbase = rblk * 512;
  const int b = nbase >> 12, hw0 = nbase & 4095;   // 512 | 4096 -> no b crossing
  const float* zb = z + (size_t)b * (C_DIM * HWSZ) + hw0;

  // ---- B resident load: 128 KB via cp.async ----
  #pragma unroll
  for (int i = 0; i < 32; ++i){
    int id = t + i * 256;
    int s = id >> 12, rem = id & 4095;
    int code = rem >> 5, c16 = rem & 31;
    int ch = c16 >> 2, j = c16 & 3;
    const __half* src = g_es + ((size_t)s * K_CODES + slice * 128 + code) * C_DIM + ch * 32 + j * 8;
    CPASYNC16(sb + SM_B + ch * 16384 + s * 8192 + swz((uint32_t)(code * 64 + j * 16)), src);
  }
  CPCOMMIT();

  // e2 for this warp's 4 codes (per lane-group) -> registers
  float e2r[2][2];
  #pragma unroll
  for (int na = 0; na < 2; ++na)
    #pragma unroll
    for (int c2 = 0; c2 < 2; ++c2)
      e2r[na][c2] = __ldg(&g_e2[slice * 128 + w * 16 + na * 8 + (l & 3) * 2 + c2]);

  const int arow = t & 31, acg = t >> 5;   // thread -> (row, c-chunk) for A loads

  // A tile prefetch -> regs
  float za[32];
  #pragma unroll
  for (int k = 0; k < 32; ++k)
    za[k] = __ldg(zb + (size_t)(acg * 32 + k) * HWSZ + arow);

  // split + STS helper
  auto sts_tile = [&](int buf){
    uint32_t p0[16], p1[16];
    #pragma unroll
    for (int j2 = 0; j2 < 16; ++j2){
      uint32_t a0, a1, b0, b1;
      split2(za[2 * j2], a0, a1);
      split2(za[2 * j2 + 1], b0, b1);
      p0[j2] = a0 | (b0 << 16);
      p1[j2] = a1 | (b1 << 16);
    }
    uint32_t base = sb + SM_A + (uint32_t)buf * 32768 + (uint32_t)acg * 4096;
    #pragma unroll
    for (int q = 0; q < 4; ++q){
      uint32_t ad = swz((uint32_t)(arow * 64 + q * 16));
      STS128(base + ad,        p0[4*q], p0[4*q+1], p0[4*q+2], p0[4*q+3]);
      STS128(base + 2048 + ad, p1[4*q], p1[4*q+1], p1[4*q+2], p1[4*q+3]);
    }
  };

  sts_tile(0);
  asm volatile("cp.async.wait_group 0;" ::: "memory");
  __syncthreads();

  const int pa[3] = {0,0,1}, pb[3] = {0,1,0};
  const uint32_t nrow = (uint32_t)(w * 16 + ((l >> 4) << 3) + (l & 7));

  for (int tile = 0; tile < 16; ++tile){
    const uint32_t Abuf = sb + SM_A + (uint32_t)(tile & 1) * 32768;

    // prefetch next A tile into regs (lands during MMA)
    if (tile + 1 < 16){
      #pragma unroll
      for (int k = 0; k < 32; ++k)
        za[k] = __ldg(zb + (size_t)(acg * 32 + k) * HWSZ + (tile + 1) * 32 + arow);
    }

    float acc[2][2][4];
    #pragma unroll
    for (int ma = 0; ma < 2; ++ma)
      #pragma unroll
      for (int na = 0; na < 2; ++na)
        #pragma unroll
        for (int q = 0; q < 4; ++q) acc[ma][na][q] = 0.f;

    #pragma unroll
    for (int ch = 0; ch < 8; ++ch){
      #pragma unroll
      for (int k16l = 0; k16l < 2; ++k16l){
        uint32_t af[2][2][4], bf[2][2][2];
        #pragma unroll
        for (int s = 0; s < 2; ++s){
          #pragma unroll
          for (int ma = 0; ma < 2; ++ma){
            uint32_t row = (uint32_t)(ma * 16 + (l & 7) + ((l >> 3) & 1) * 8);
            uint32_t ad = Abuf + ch * 4096 + s * 2048 + swz(row * 64 + k16l * 32 + ((l >> 4) << 4));
            LDSM_X4(af[s][ma][0], af[s][ma][1], af[s][ma][2], af[s][ma][3], ad);
          }
          uint32_t bd = sb + SM_B + ch * 16384 + s * 8192 + swz(nrow * 64 + k16l * 32 + (((l >> 3) & 1) << 4));
          LDSM_X4(bf[s][0][0], bf[s][0][1], bf[s][1][0], bf[s][1][1], bd);
        }
        #pragma unroll
        for (int p = 0; p < 3; ++p){
          const int sa = pa[p], sbp = pb[p];
          #pragma unroll
          for (int ma = 0; ma < 2; ++ma)
            #pragma unroll
            for (int na = 0; na < 2; ++na)
              MMA16816(acc[ma][na][0], acc[ma][na][1], acc[ma][na][2], acc[ma][na][3],
                       af[sa][ma][0], af[sa][ma][1], af[sa][ma][2], af[sa][ma][3],
                       bf[sbp][na][0], bf[sbp][na][1]);
        }
      }
    }

    // ---- per-tile argmin over this warp's 16 codes, then u64 atomicMin merge ----
    #pragma unroll
    for (int ma = 0; ma < 2; ++ma){
      #pragma unroll
      for (int h = 0; h < 2; ++h){
        int row = ma * 16 + (l >> 2) + h * 8;
        int n = nbase + tile * 32 + row;
        float z2v = __ldg(&g_z2[n]);
        float bv = 3.4028235e38f; int bi = 0;
        #pragma unroll
        for (int na = 0; na < 2; ++na){
          #pragma unroll
          for (int c2 = 0; c2 < 2; ++c2){
            int code = slice * 128 + w * 16 + na * 8 + (l & 3) * 2 + c2;
            float dot = acc[ma][na][h * 2 + c2] * EINVSCALE;
            float sd = __fadd_rn(z2v, e2r[na][c2]);
            float dist = __fsub_rn(sd, __fmul_rn(2.0f, dot));
            if (dist < bv){ bv = dist; bi = code; }
          }
        }
        #pragma unroll
        for (int m = 1; m <= 2; m <<= 1){
          float ov = __shfl_xor_sync(0xffffffffu, bv, m);
          int   oi = __shfl_xor_sync(0xffffffffu, bi, m);
          if (ov < bv || (ov == bv && oi < bi)){ bv = ov; bi = oi; }
        }
        if ((l & 3) == 0){
          unsigned long long pk = ((unsigned long long)__float_as_uint(bv) << 32) | (unsigned)bi;
          atomicMin(&g_min[n], pk);
        }
      }
    }

    // split + STS next tile into other buffer (freed by the previous tile's barrier)
    if (tile + 1 < 16) sts_tile((tile + 1) & 1);
    __syncthreads();
  }
}

// ---------------- epilogue: gather zq, straight-through, idx, loss partials ----------------
__global__ __launch_bounds__(256, 1) void vq_epi(const float* __restrict__ z,
                                                 const float* __restrict__ emb,
                                                 float* __restrict__ out,
                                                 int out_size){
  __shared__ int sidx[128];
  __shared__ float red[256];
  const int t = threadIdx.x;
  const int n0 = blockIdx.x * 128;
  if (t < 128){
    int code = (int)(unsigned)(g_min[n0 + t] & 0xFFFFFFFFull);
    sidx[t] = code;
    if (out_size >= NZQ + N_ROWS) out[NZQ + n0 + t] = (float)code;
  }
  __syncthreads();
  const int b = n0 >> 12, hw0 = n0 & 4095;
  const size_t base = (size_t)b * (C_DIM * HWSZ) + hw0;
  const int i = t & 127, half = t >> 7;
  const int code = sidx[i];
  const float* erow = emb + (size_t)code * C_DIM;
  float acc = 0.f;
  const bool wr = (out_size >= NZQ);
  #pragma unroll 4
  for (int c = half; c < 256; c += 2){
    float e  = __ldg(&erow[c]);
    size_t a = base + (size_t)c * HWSZ + i;
    float zp = z[a];
    float d  = __fsub_rn(e, zp);
    if (wr) out[a] = __fadd_rn(zp, d);
    acc = __fadd_rn(acc, __fmul_rn(d, d));
  }
  red[t] = acc;
  __syncthreads();
  for (int s = 128; s > 0; s >>= 1){
    if (t < s) red[t] = __fadd_rn(red[t], red[t + s]);
    __syncthreads();
  }
  if (t == 0) g_partial[blockIdx.x] = red[0];
}

// ---------------- final loss ----------------
__global__ void vq_fin(float* __restrict__ out, int out_size){
  __shared__ double dred[256];
  const int t = threadIdx.x;
  double s = 0.0;
  for (int ii = t; ii < 1024; ii += 256) s += (double)g_partial[ii];
  dred[t] = s;
  __syncthreads();
  for (int k = 128; k > 0; k >>= 1){
    if (t < k) dred[t] += dred[t + k];
    __syncthreads();
  }
  if (t == 0 && out_size >= NZQ + N_ROWS + 1){
    float m1 = (float)(dred[0] / 33554432.0);
    float loss = __fsub_rn(m1, __fmul_rn(0.25f, m1));
    out[NZQ + N_ROWS] = loss;
  }
}

extern "C" void kernel_launch(void* const* d_in, const int* in_sizes, int n_in,
                              void* d_out, int out_size){
  const float* z   = (const float*)d_in[0];
  const float* emb = (const float*)d_in[1];
  float* out = (float*)d_out;
  (void)in_sizes; (void)n_in;

  cudaFuncSetAttribute(vq_main, cudaFuncAttributeMaxDynamicSharedMemorySize, SM_TOTAL);

  prep_e<<<K_CODES, C_DIM>>>(emb);
  prep_z2<<<N_ROWS / 256, 256>>>(z);
  init_min<<<N_ROWS / 256, 256>>>();
  vq_main<<<2048, 256, SM_TOTAL>>>(z);
  vq_epi<<<N_ROWS / 128, 256>>>(z, emb, out, out_size);
  vq_fin<<<1, 256>>>(out, out_size);
}

// round 8
// speedup vs baseline: 1.2553x; 1.2553x over previous
#include <cuda_runtime.h>
#include <cuda_fp16.h>
#include <cstdint>

#define N_ROWS  131072
#define C_DIM   256
#define K_CODES 1024
#define NZQ     33554432
#define HWSZ    4096

#define ESCALE    4096.0f          // 2^12: lift emb splits out of fp16 subnormal range
#define EINVSCALE 0.000244140625f  // 2^-12 (exact)

// ---- device scratch ----
__device__ __half g_es[2u * K_CODES * C_DIM];   // emb fp16 2-splits of (e * 2^12)
__device__ float  g_e2[K_CODES];
__device__ float  g_partial[1024];

__device__ __forceinline__ uint32_t smem_u32(const void* p){
  uint32_t a;
  asm("{ .reg .u64 t; cvta.to.shared.u64 t, %1; cvt.u32.u64 %0, t; }" : "=r"(a) : "l"(p));
  return a;
}
__device__ __forceinline__ uint32_t swz(uint32_t off){ return off ^ ((off >> 3) & 0x70); }

__device__ __forceinline__ void split2(float v, uint32_t &s0, uint32_t &s1){
  __half h0 = __float2half_rn(v);
  float r  = __fsub_rn(v, __half2float(h0));
  __half h1 = __float2half_rn(r);
  s0 = (uint32_t)__half_as_ushort(h0);
  s1 = (uint32_t)__half_as_ushort(h1);
}

#define CPASYNC16(dst, src) \
  asm volatile("cp.async.cg.shared.global [%0], [%1], 16;" :: "r"(dst), "l"(src))
#define CPCOMMIT() asm volatile("cp.async.commit_group;")

#define LDSM_X4(r0,r1,r2,r3,addr) \
  asm volatile("ldmatrix.sync.aligned.m8n8.x4.shared.b16 {%0,%1,%2,%3}, [%4];" \
    : "=r"(r0), "=r"(r1), "=r"(r2), "=r"(r3) : "r"(addr))

#define MMA16816(c0,c1,c2,c3,a0,a1,a2,a3,b0,b1) \
  asm volatile("mma.sync.aligned.m16n8k16.row.col.f32.f16.f16.f32 " \
    "{%0,%1,%2,%3}, {%4,%5,%6,%7}, {%8,%9}, {%0,%1,%2,%3};" \
    : "+f"(c0), "+f"(c1), "+f"(c2), "+f"(c3) \
    : "r"(a0), "r"(a1), "r"(a2), "r"(a3), "r"(b0), "r"(b1))

#define STS128(addr, a0, a1, a2, a3) \
  asm volatile("st.shared.v4.b32 [%0], {%1,%2,%3,%4};" :: "r"(addr), "r"(a0), "r"(a1), "r"(a2), "r"(a3) : "memory")

// ---------------- prep: emb fp16 splits (scaled) + ||e||^2 ----------------
__global__ void prep_e(const float* __restrict__ emb){
  int k = blockIdx.x, c = threadIdx.x;
  float v = emb[k * C_DIM + c];
  uint32_t s0, s1;
  split2(v * ESCALE, s0, s1);
  g_es[(0u * K_CODES + k) * C_DIM + c] = __ushort_as_half((unsigned short)s0);
  g_es[(1u * K_CODES + k) * C_DIM + c] = __ushort_as_half((unsigned short)s1);
  __shared__ float red[C_DIM];
  red[c] = __fmul_rn(v, v);
  __syncthreads();
  for (int s = 128; s > 0; s >>= 1){
    if (c < s) red[c] = __fadd_rn(red[c], red[c + s]);
    __syncthreads();
  }
  if (c == 0) g_e2[k] = red[0];
}

// ---------------- main: 512-thread CTA, A-resident, 32 fat windows ----------------
// smem: A[4 kc][2 s][128 r][64 c] = 128K | B[2 buf][2 s][128 code][64 c] = 64K | misc
#define SM_A      0
#define SM_B      131072
#define OFF_E2S   196608
#define OFF_Z2S   200704
#define OFF_SMINV 201216
#define OFF_SMINI 203264
#define OFF_SIDX  205312
#define OFF_RED   205824
#define SM_TOTAL  207872

__global__ __launch_bounds__(512, 1) void vq_main(const float* __restrict__ z,
                                                  const float* __restrict__ emb,
                                                  float* __restrict__ out,
                                                  int out_size){
  extern __shared__ char smem[];
  const uint32_t sb = smem_u32(smem);
  float* e2s   = (float*)(smem + OFF_E2S);
  float* z2s   = (float*)(smem + OFF_Z2S);
  float* sminv = (float*)(smem + OFF_SMINV);
  int*   smini = (int*)(smem + OFF_SMINI);
  int*   sidx  = (int*)(smem + OFF_SIDX);
  float* red   = (float*)(smem + OFF_RED);

  const int t = threadIdx.x, w = t >> 5, l = t & 31;
  const int wm = (w & 3) * 32;        // 4 m-warps x 32 rows
  const int g  = w >> 2;              // 4 n-warp groups
  const int wn = g * 32;              // 32 codes per warp within 128-code tile
  const int n0 = blockIdx.x * 128;
  const int b  = n0 >> 12, hw0 = n0 & 4095;
  const float* zb = z + (size_t)b * (C_DIM * HWSZ) + hw0;

  // ---- B cp.async: one stage = [2 s][128 code][64 c] = 32KB ----
  auto issue = [&](int stage){
    const int nt2 = stage >> 2, kc2 = stage & 3, buf2 = stage & 1;
    #pragma unroll
    for (int i = 0; i < 4; ++i){
      int id = t + i * 512;           // 0..2047 x 16B
      int s = id >> 10, rem = id & 1023;
      int r = rem >> 3, j = rem & 7;
      const __half* src = g_es + ((size_t)s * K_CODES + nt2 * 128 + r) * C_DIM + kc2 * 64 + j * 8;
      CPASYNC16(sb + SM_B + buf2 * 32768 + s * 16384 + swz((uint32_t)(r * 128 + j * 16)), src);
    }
    CPCOMMIT();
  };

  issue(0);
  issue(1);

  // ---- phase 1: 4 thr/row split z -> A smem; then t<128 computes z2 sequentially ----
  {
    const int row = t & 127, q = t >> 7;   // q = kc region (64 c)
    #pragma unroll
    for (int cg = 0; cg < 8; ++cg){
      uint32_t p0[4], p1[4];
      #pragma unroll
      for (int j2 = 0; j2 < 4; ++j2){
        int c = q * 64 + cg * 8 + j2 * 2;
        float va = __ldg(zb + (size_t)c * HWSZ + row);
        float vb = __ldg(zb + (size_t)(c + 1) * HWSZ + row);
        uint32_t a0, a1, b0, b1;
        split2(va, a0, a1); split2(vb, b0, b1);
        p0[j2] = a0 | (b0 << 16);
        p1[j2] = a1 | (b1 << 16);
      }
      uint32_t ad = swz((uint32_t)(row * 128 + cg * 16));
      STS128(sb + SM_A + q * 32768 + ad,         p0[0], p0[1], p0[2], p0[3]);
      STS128(sb + SM_A + q * 32768 + 16384 + ad, p1[0], p1[1], p1[2], p1[3]);
    }
  }
  for (int i = t; i < 1024; i += 512) e2s[i] = g_e2[i];
  if (t < 128){
    float acc = 0.f;
    #pragma unroll 8
    for (int c = 0; c < 256; ++c){
      float v = __ldg(zb + (size_t)c * HWSZ + t);
      acc = __fadd_rn(acc, __fmul_rn(v, v));
    }
    z2s[t] = acc;
  }
  __syncthreads();

  float z2r[4];
  #pragma unroll
  for (int slot = 0; slot < 4; ++slot){
    int row = wm + (slot >> 1) * 16 + (l >> 2) + (slot & 1) * 8;
    z2r[slot] = z2s[row];
  }

  float acc[2][4][4];
  float minv[4]; int mini[4];
  #pragma unroll
  for (int s2 = 0; s2 < 4; ++s2){ minv[s2] = 3.4028235e38f; mini[s2] = 0; }

  const int pa[3] = {0,0,1}, pb[3] = {0,1,0};

  for (int st = 0; st < 32; ++st){
    const int nt = st >> 2, kc = st & 3, buf = st & 1;

    if (st < 31) asm volatile("cp.async.wait_group 1;" ::: "memory");
    else         asm volatile("cp.async.wait_group 0;" ::: "memory");
    __syncthreads();

    if (kc == 0){
      #pragma unroll
      for (int ma = 0; ma < 2; ++ma)
        #pragma unroll
        for (int na = 0; na < 4; ++na)
          #pragma unroll
          for (int q = 0; q < 4; ++q) acc[ma][na][q] = 0.f;
    }

    const uint32_t Ab = sb + SM_A + (uint32_t)kc * 32768;
    const uint32_t Bb = sb + SM_B + (uint32_t)buf * 32768;
    #pragma unroll
    for (int k16 = 0; k16 < 4; ++k16){
      const uint32_t kbyte = (uint32_t)(k16 * 32);
      uint32_t af[2][2][4], bf[2][4][2];
      #pragma unroll
      for (int s = 0; s < 2; ++s){
        #pragma unroll
        for (int ma = 0; ma < 2; ++ma){
          uint32_t row = (uint32_t)(wm + ma * 16 + (l & 7) + ((l >> 3) & 1) * 8);
          uint32_t ad = Ab + s * 16384 + swz(row * 128 + kbyte + ((l >> 4) << 4));
          LDSM_X4(af[s][ma][0], af[s][ma][1], af[s][ma][2], af[s][ma][3], ad);
        }
        #pragma unroll
        for (int p = 0; p < 2; ++p){
          uint32_t nrow = (uint32_t)(wn + p * 16 + ((l >> 4) << 3) + (l & 7));
          uint32_t bd = Bb + s * 16384 + swz(nrow * 128 + kbyte + (((l >> 3) & 1) << 4));
          LDSM_X4(bf[s][2*p][0], bf[s][2*p][1], bf[s][2*p+1][0], bf[s][2*p+1][1], bd);
        }
      }
      #pragma unroll
      for (int p = 0; p < 3; ++p){
        const int sa = pa[p], sbp = pb[p];
        #pragma unroll
        for (int ma = 0; ma < 2; ++ma)
          #pragma unroll
          for (int na = 0; na < 4; ++na)
            MMA16816(acc[ma][na][0], acc[ma][na][1], acc[ma][na][2], acc[ma][na][3],
                     af[sa][ma][0], af[sa][ma][1], af[sa][ma][2], af[sa][ma][3],
                     bf[sbp][na][0], bf[sbp][na][1]);
      }
    }
    __syncthreads();
    if (st + 2 < 32) issue(st + 2);

    if (kc == 3){
      #pragma unroll
      for (int na = 0; na < 4; ++na){
        #pragma unroll
        for (int c2 = 0; c2 < 2; ++c2){
          int code = nt * 128 + wn + (na >> 1) * 16 + (na & 1) * 8 + (l & 3) * 2 + c2;
          float e2v = e2s[code];
          #pragma unroll
          for (int ma = 0; ma < 2; ++ma){
            #pragma unroll
            for (int h = 0; h < 2; ++h){
              int slot = ma * 2 + h;
              float dot = acc[ma][na][h * 2 + c2] * EINVSCALE;
              float sd = __fadd_rn(z2r[slot], e2v);
              float dist = __fsub_rn(sd, __fmul_rn(2.0f, dot));
              if (dist < minv[slot]){ minv[slot] = dist; mini[slot] = code; }
            }
          }
        }
      }
    }
  }

  // ---- argmin reduce: 4 lanes per row, then 4 n-warp groups via smem ----
  #pragma unroll
  for (int slot = 0; slot < 4; ++slot){
    #pragma unroll
    for (int m = 1; m <= 2; m <<= 1){
      float ov = __shfl_xor_sync(0xffffffffu, minv[slot], m);
      int   oi = __shfl_xor_sync(0xffffffffu, mini[slot], m);
      if (ov < minv[slot] || (ov == minv[slot] && oi < mini[slot])){ minv[slot] = ov; mini[slot] = oi; }
    }
  }
  if ((l & 3) == 0){
    #pragma unroll
    for (int slot = 0; slot < 4; ++slot){
      int row = wm + (slot >> 1) * 16 + (l >> 2) + (slot & 1) * 8;
      sminv[g * 128 + row] = minv[slot]; smini[g * 128 + row] = mini[slot];
    }
  }
  __syncthreads();
  if (t < 128){
    float bv = sminv[t]; int bi = smini[t];
    #pragma unroll
    for (int gg = 1; gg < 4; ++gg){
      float ov = sminv[gg * 128 + t]; int oi = smini[gg * 128 + t];
      if (ov < bv || (ov == bv && oi < bi)){ bv = ov; bi = oi; }
    }
    sidx[t] = bi;
    if (out_size >= NZQ + N_ROWS) out[NZQ + n0 + t] = (float)bi;
  }
  __syncthreads();

  // ---- fused epilogue: gather zq, straight-through output, loss partial ----
  {
    const int i = t & 127, q = t >> 7;
    const int code = sidx[i];
    const float* erow = emb + (size_t)code * C_DIM;
    float lacc = 0.f;
    const bool wr = (out_size >= NZQ);
    #pragma unroll 4
    for (int c = q; c < 256; c += 4){
      float e  = __ldg(&erow[c]);
      size_t a = (size_t)b * (C_DIM * HWSZ) + hw0 + (size_t)c * HWSZ + i;
      float zp = z[a];
      float d  = __fsub_rn(e, zp);
      if (wr) out[a] = __fadd_rn(zp, d);
      lacc = __fadd_rn(lacc, __fmul_rn(d, d));
    }
    red[t] = lacc;
    __syncthreads();
    for (int s = 256; s > 0; s >>= 1){
      if (t < s) red[t] = __fadd_rn(red[t], red[t + s]);
      __syncthreads();
    }
    if (t == 0) g_partial[blockIdx.x] = red[0];
  }
}

// ---------------- final loss ----------------
__global__ void vq_fin(float* __restrict__ out, int out_size){
  __shared__ double dred[256];
  const int t = threadIdx.x;
  double s = 0.0;
  for (int ii = t; ii < 1024; ii += 256) s += (double)g_partial[ii];
  dred[t] = s;
  __syncthreads();
  for (int k = 128; k > 0; k >>= 1){
    if (t < k) dred[t] += dred[t + k];
    __syncthreads();
  }
  if (t == 0 && out_size >= NZQ + N_ROWS + 1){
    float m1 = (float)(dred[0] / 33554432.0);
    float loss = __fsub_rn(m1, __fmul_rn(0.25f, m1));
    out[NZQ + N_ROWS] = loss;
  }
}

extern "C" void kernel_launch(void* const* d_in, const int* in_sizes, int n_in,
                              void* d_out, int out_size){
  const float* z   = (const float*)d_in[0];
  const float* emb = (const float*)d_in[1];
  float* out = (float*)d_out;
  (void)in_sizes; (void)n_in;

  cudaFuncSetAttribute(vq_main, cudaFuncAttributeMaxDynamicSharedMemorySize, SM_TOTAL);

  prep_e<<<K_CODES, C_DIM>>>(emb);
  vq_main<<<N_ROWS / 128, 512, SM_TOTAL>>>(z, emb, out, out_size);
  vq_fin<<<1, 256>>>(out, out_size);
}